// round 3
// baseline (speedup 1.0000x reference)
#include <cuda_runtime.h>
#include <cstdint>

#define MAX_NODES 100000
#define MAX_EDGES 1600000

// Scratch (allocation-free: device globals). 256B-aligned for float4/red.v4 access.
__device__ __align__(256) float g_h[(size_t)MAX_NODES * 128];
__device__ __align__(256) float g_y[(size_t)MAX_NODES * 128];
__device__ __align__(256) float g_agg[(size_t)MAX_NODES * 128];
__device__ __align__(256) float g_deg[MAX_NODES];
__device__ __align__(256) float g_dinv[MAX_NODES];
__device__ int g_i64;   // 1 if edge_index is int64, 0 if int32

// ---------------------------------------------------------------------------
// Edge dtype detection: int64 edge values < 1e5 have all-zero high words at
// odd int32 positions; int32 edge data there is uniform [0,1e5) — never all 0.
// Reads only the first min(2048, n_words_int32_safe) words (safe either way).
// ---------------------------------------------------------------------------
__global__ void detect_dtype_kernel(const int* __restrict__ ei32, int n_elem) {
    if (threadIdx.x == 0 && blockIdx.x == 0) {
        int acc = 0;
        int lim = n_elem < 2048 ? n_elem : 2048;  // n_elem int32 words exist in both cases
        for (int i = 1; i < lim; i += 2) acc |= ei32[i];
        g_i64 = (acc == 0) ? 1 : 0;
    }
}

// element index -> int32 word index (lo word for int64, little-endian)
__device__ __forceinline__ int edge_val(const int* __restrict__ ei32, size_t elem, int sh) {
    return ei32[elem << sh];
}

// ---------------------------------------------------------------------------
// Degree / normalization
// ---------------------------------------------------------------------------
__global__ void count_deg_kernel(const int* __restrict__ ei32, int E, int M) {
    int e = blockIdx.x * blockDim.x + threadIdx.x;
    if (e < E) {
        int sh = g_i64;
        int d = edge_val(ei32, (size_t)E + e, sh);
        if ((unsigned)d < (unsigned)M) atomicAdd(&g_deg[d], 1.0f);
    }
}

__global__ void dinv_kernel(int M) {
    int i = blockIdx.x * blockDim.x + threadIdx.x;
    if (i < M) g_dinv[i] = rsqrtf(g_deg[i] + 1.0f);  // +1 self loop
}

// ---------------------------------------------------------------------------
// GEMM: H[M,NC] = X[M,128] @ W[128,NC]   (fp32 SIMT, W + X tile in SMEM)
// ---------------------------------------------------------------------------
template <int NC>
__global__ void gemm_kernel(const float* __restrict__ X, const float* __restrict__ W,
                            float* __restrict__ H, int M) {
    extern __shared__ float sh[];
    float* shW = sh;                       // 128*NC floats
    float* shX = sh + 128 * NC;            // ROWS*128 floats
    constexpr int ROWS = (NC == 128) ? 64 : 128;

    const int tid = threadIdx.x;
    const int rowBase = blockIdx.x * ROWS;

    for (int i = tid; i < 128 * NC / 4; i += 256)
        ((float4*)shW)[i] = ((const float4*)W)[i];

    for (int i = tid; i < ROWS * 32; i += 256) {
        int r = i >> 5;
        int gr = rowBase + r;
        float4 v = make_float4(0.f, 0.f, 0.f, 0.f);
        if (gr < M) v = ((const float4*)X)[(size_t)gr * 32 + (i & 31)];
        ((float4*)shX)[i] = v;
    }
    __syncthreads();

    const int warp = tid >> 5, lane = tid & 31;
    constexpr int LPR = NC / 4;            // lanes per row-group (32 or 16)
    constexpr int RPW = ROWS / 8;          // rows per warp (8 or 16)
    const int grp = lane / LPR;
    const int c0 = (lane % LPR) * 4;
    const int r0 = warp * RPW + grp * 8;

    float4 acc[8];
    #pragma unroll
    for (int r = 0; r < 8; ++r) acc[r] = make_float4(0.f, 0.f, 0.f, 0.f);

    #pragma unroll 4
    for (int k4 = 0; k4 < 32; ++k4) {
        float4 w0 = *(const float4*)&shW[(4 * k4 + 0) * NC + c0];
        float4 w1 = *(const float4*)&shW[(4 * k4 + 1) * NC + c0];
        float4 w2 = *(const float4*)&shW[(4 * k4 + 2) * NC + c0];
        float4 w3 = *(const float4*)&shW[(4 * k4 + 3) * NC + c0];
        #pragma unroll
        for (int r = 0; r < 8; ++r) {
            float4 xv = *(const float4*)&shX[(r0 + r) * 128 + 4 * k4];
            acc[r].x += xv.x * w0.x + xv.y * w1.x + xv.z * w2.x + xv.w * w3.x;
            acc[r].y += xv.x * w0.y + xv.y * w1.y + xv.z * w2.y + xv.w * w3.y;
            acc[r].z += xv.x * w0.z + xv.y * w1.z + xv.z * w2.z + xv.w * w3.z;
            acc[r].w += xv.x * w0.w + xv.y * w1.w + xv.z * w2.w + xv.w * w3.w;
        }
    }

    #pragma unroll
    for (int r = 0; r < 8; ++r) {
        int gr = rowBase + r0 + r;
        if (gr < M) *(float4*)&H[(size_t)gr * NC + c0] = acc[r];
    }
}

// ---------------------------------------------------------------------------
// Scatter-add: agg[dst] += h[src] * dinv[src]*dinv[dst]  via vector red.global
// ---------------------------------------------------------------------------
__device__ __forceinline__ void red_add_v4(float* p, float4 v) {
    asm volatile("red.global.add.v4.f32 [%0], {%1, %2, %3, %4};"
                 :: "l"(p), "f"(v.x), "f"(v.y), "f"(v.z), "f"(v.w) : "memory");
}

template <int LOGC>  // LOGC: log2(float4 chunks per row) — 5 for C=128, 4 for C=64
__global__ void scatter_kernel(const float* __restrict__ H,
                               const int* __restrict__ ei32, int E, int M) {
    constexpr int C4 = 1 << LOGC;
    constexpr int NC = C4 * 4;
    long long idx = (long long)blockIdx.x * blockDim.x + threadIdx.x;
    if (idx >= (long long)E * C4) return;
    int e = (int)(idx >> LOGC);
    int j = (int)(idx & (C4 - 1));
    int sh = g_i64;
    int s = edge_val(ei32, (size_t)e, sh);
    int d = edge_val(ei32, (size_t)E + e, sh);
    if ((unsigned)s >= (unsigned)M || (unsigned)d >= (unsigned)M) return;
    float norm = g_dinv[s] * g_dinv[d];
    float4 v = __ldg((const float4*)&H[(size_t)s * NC + j * 4]);
    v.x *= norm; v.y *= norm; v.z *= norm; v.w *= norm;
    red_add_v4(&g_agg[(size_t)d * NC + j * 4], v);
}

// ---------------------------------------------------------------------------
// Finalize: out = [relu](agg + h*dinv^2 + b)
// ---------------------------------------------------------------------------
template <int LOGC, bool RELU>
__global__ void finalize_kernel(const float* __restrict__ H, const float* __restrict__ b,
                                float* __restrict__ out, int M) {
    constexpr int C4 = 1 << LOGC;
    int idx = blockIdx.x * blockDim.x + threadIdx.x;
    if (idx >= M * C4) return;
    int row = idx >> LOGC;
    int j = idx & (C4 - 1);
    float di = g_dinv[row];
    float s2 = di * di;
    float4 a = ((const float4*)g_agg)[idx];
    float4 h = __ldg((const float4*)H + idx);
    float4 bv = __ldg((const float4*)b + j);
    float4 v;
    v.x = a.x + h.x * s2 + bv.x;
    v.y = a.y + h.y * s2 + bv.y;
    v.z = a.z + h.z * s2 + bv.z;
    v.w = a.w + h.w * s2 + bv.w;
    if (RELU) {
        v.x = fmaxf(v.x, 0.f); v.y = fmaxf(v.y, 0.f);
        v.z = fmaxf(v.z, 0.f); v.w = fmaxf(v.w, 0.f);
    }
    ((float4*)out)[idx] = v;
}

// ---------------------------------------------------------------------------
// Launch — inputs identified by element count (all distinct), not by order:
//   x: 12,800,000   W1: 16,384   b1: 128   W2: 8,192   b2: 64   edge: 3,200,000
// ---------------------------------------------------------------------------
extern "C" void kernel_launch(void* const* d_in, const int* in_sizes, int n_in,
                              void* d_out, int out_size) {
    const float* x = nullptr; const float* W1 = nullptr; const float* b1 = nullptr;
    const float* W2 = nullptr; const float* b2 = nullptr;
    const int* ei32 = nullptr; int e_elems = 0;
    int x_elems = 0;

    // Largest buffer = x, second largest = edge_index; small ones by exact rank.
    // Find by relative size ordering to avoid hardcoding absolute counts.
    int idxs[8]; for (int i = 0; i < n_in; ++i) idxs[i] = i;
    // simple selection sort by size descending
    for (int i = 0; i < n_in; ++i)
        for (int j = i + 1; j < n_in; ++j)
            if (in_sizes[idxs[j]] > in_sizes[idxs[i]]) { int t = idxs[i]; idxs[i] = idxs[j]; idxs[j] = t; }
    // ranks: 0=x, 1=edge, 2=W1, 3=W2, 4=b1, 5=b2
    x   = (const float*)d_in[idxs[0]]; x_elems = in_sizes[idxs[0]];
    ei32 = (const int*) d_in[idxs[1]]; e_elems = in_sizes[idxs[1]];
    W1  = (const float*)d_in[idxs[2]];
    W2  = (const float*)d_in[idxs[3]];
    b1  = (const float*)d_in[idxs[4]];
    b2  = (const float*)d_in[idxs[5]];

    const int M = x_elems / 128;   // 100000
    const int E = e_elems / 2;     // 1600000

    void *p_deg, *p_agg, *p_h, *p_y;
    cudaGetSymbolAddress(&p_deg, g_deg);
    cudaGetSymbolAddress(&p_agg, g_agg);
    cudaGetSymbolAddress(&p_h,   g_h);
    cudaGetSymbolAddress(&p_y,   g_y);

    constexpr int SMEM = 98304;
    cudaFuncSetAttribute(gemm_kernel<128>, cudaFuncAttributeMaxDynamicSharedMemorySize, SMEM);
    cudaFuncSetAttribute(gemm_kernel<64>,  cudaFuncAttributeMaxDynamicSharedMemorySize, SMEM);

    // Edge dtype detection + normalization (deterministic every call)
    detect_dtype_kernel<<<1, 32>>>(ei32, e_elems);
    cudaMemsetAsync(p_deg, 0, (size_t)M * sizeof(float));
    count_deg_kernel<<<(E + 255) / 256, 256>>>(ei32, E, M);
    dinv_kernel<<<(M + 255) / 256, 256>>>(M);

    // ---- Layer 1 ----
    gemm_kernel<128><<<(M + 63) / 64, 256, SMEM>>>(x, W1, (float*)p_h, M);
    cudaMemsetAsync(p_agg, 0, (size_t)M * 128 * sizeof(float));
    {
        long long t = (long long)E * 32;
        scatter_kernel<5><<<(unsigned)((t + 255) / 256), 256>>>((const float*)p_h, ei32, E, M);
    }
    finalize_kernel<5, true><<<(M * 32 + 255) / 256, 256>>>(
        (const float*)p_h, b1, (float*)p_y, M);

    // ---- Layer 2 ----
    gemm_kernel<64><<<(M + 127) / 128, 256, SMEM>>>((const float*)p_y, W2, (float*)p_h, M);
    cudaMemsetAsync(p_agg, 0, (size_t)M * 64 * sizeof(float));
    {
        long long t = (long long)E * 16;
        scatter_kernel<4><<<(unsigned)((t + 255) / 256), 256>>>((const float*)p_h, ei32, E, M);
    }
    finalize_kernel<4, false><<<(M * 16 + 255) / 256, 256>>>(
        (const float*)p_h, b2, (float*)d_out, M);
}

// round 7
// speedup vs baseline: 1.6437x; 1.6437x over previous
#include <cuda_runtime.h>
#include <cstdint>

#define MAX_NODES 100000
#define MAX_EDGES 1600000
#define SCAN_BLK 1024

// Scratch (allocation-free device globals); 256B-aligned for float4 access.
__device__ __align__(256) float g_h[(size_t)MAX_NODES * 128];   // h' = (X@W)*dinv
__device__ __align__(256) float g_y[(size_t)MAX_NODES * 128];   // layer-1 output
__device__ __align__(256) float g_dinv[MAX_NODES];
__device__ __align__(256) int   g_degi[MAX_NODES];
__device__ __align__(256) int   g_rtmp[MAX_NODES];              // block-local exclusive scans
__device__ __align__(256) int   g_row_ptr[MAX_NODES + 1];
__device__ __align__(256) int   g_cursor[MAX_NODES];
__device__ __align__(256) int   g_csr_src[MAX_EDGES];
__device__ __align__(256) int   g_bsums[(MAX_NODES + SCAN_BLK - 1) / SCAN_BLK + 1];
__device__ int g_i64;   // 1 if edge_index is int64, 0 if int32

// ---------------------------------------------------------------------------
// Edge dtype detection: int64 values < 1e5 have all-zero high int32 words.
// ---------------------------------------------------------------------------
__global__ void detect_dtype_kernel(const int* __restrict__ ei32, int n_elem) {
    if (threadIdx.x == 0 && blockIdx.x == 0) {
        int acc = 0;
        int lim = n_elem < 2048 ? n_elem : 2048;
        for (int i = 1; i < lim; i += 2) acc |= ei32[i];
        g_i64 = (acc == 0) ? 1 : 0;
    }
}

__device__ __forceinline__ int edge_val(const int* __restrict__ ei32, size_t elem, int sh) {
    return ei32[elem << sh];
}

// ---------------------------------------------------------------------------
// CSR build: degree histogram -> exclusive scan -> cursor fill
// ---------------------------------------------------------------------------
__global__ void count_deg_kernel(const int* __restrict__ ei32, int E, int M) {
    int e = blockIdx.x * blockDim.x + threadIdx.x;
    if (e < E) {
        int sh = g_i64;
        int d = edge_val(ei32, (size_t)E + e, sh);
        if ((unsigned)d < (unsigned)M) atomicAdd(&g_degi[d], 1);
    }
}

__global__ void dinv_kernel(int M) {
    int i = blockIdx.x * blockDim.x + threadIdx.x;
    if (i < M) g_dinv[i] = rsqrtf((float)g_degi[i] + 1.0f);  // +1 self loop
}

__global__ void scan1_kernel(int M) {
    __shared__ int sm[SCAN_BLK];
    int i = blockIdx.x * SCAN_BLK + threadIdx.x;
    int v = (i < M) ? g_degi[i] : 0;
    sm[threadIdx.x] = v;
    __syncthreads();
    for (int off = 1; off < SCAN_BLK; off <<= 1) {
        int t = (threadIdx.x >= off) ? sm[threadIdx.x - off] : 0;
        __syncthreads();
        sm[threadIdx.x] += t;
        __syncthreads();
    }
    if (i < M) g_rtmp[i] = sm[threadIdx.x] - v;          // exclusive within block
    if (threadIdx.x == SCAN_BLK - 1) g_bsums[blockIdx.x] = sm[SCAN_BLK - 1];
}

__global__ void scan2_kernel(int nb) {
    if (threadIdx.x == 0 && blockIdx.x == 0) {
        int run = 0;
        for (int j = 0; j < nb; ++j) { int t = g_bsums[j]; g_bsums[j] = run; run += t; }
    }
}

__global__ void scan3_kernel(int M) {
    int i = blockIdx.x * blockDim.x + threadIdx.x;
    if (i < M) {
        int rp = g_rtmp[i] + g_bsums[i / SCAN_BLK];
        g_row_ptr[i] = rp;
        g_cursor[i]  = rp;
        if (i == M - 1) g_row_ptr[M] = rp + g_degi[i];
    }
}

__global__ void fill_csr_kernel(const int* __restrict__ ei32, int E, int M) {
    int e = blockIdx.x * blockDim.x + threadIdx.x;
    if (e < E) {
        int sh = g_i64;
        int s = edge_val(ei32, (size_t)e, sh);
        int d = edge_val(ei32, (size_t)E + e, sh);
        if ((unsigned)s < (unsigned)M && (unsigned)d < (unsigned)M) {
            int pos = atomicAdd(&g_cursor[d], 1);
            g_csr_src[pos] = s;
        }
    }
}

// ---------------------------------------------------------------------------
// GEMM: H'[M,NC] = (X[M,128] @ W[128,NC]) * dinv[row]   (fp32 SIMT)
// ---------------------------------------------------------------------------
template <int NC>
__global__ void gemm_kernel(const float* __restrict__ X, const float* __restrict__ W,
                            float* __restrict__ H, int M) {
    extern __shared__ float sh[];
    float* shW = sh;                       // 128*NC floats
    float* shX = sh + 128 * NC;            // ROWS*128 floats
    constexpr int ROWS = (NC == 128) ? 64 : 128;

    const int tid = threadIdx.x;
    const int rowBase = blockIdx.x * ROWS;

    for (int i = tid; i < 128 * NC / 4; i += 256)
        ((float4*)shW)[i] = ((const float4*)W)[i];

    for (int i = tid; i < ROWS * 32; i += 256) {
        int r = i >> 5;
        int gr = rowBase + r;
        float4 v = make_float4(0.f, 0.f, 0.f, 0.f);
        if (gr < M) v = ((const float4*)X)[(size_t)gr * 32 + (i & 31)];
        ((float4*)shX)[i] = v;
    }
    __syncthreads();

    const int warp = tid >> 5, lane = tid & 31;
    constexpr int LPR = NC / 4;
    constexpr int RPW = ROWS / 8;
    const int grp = lane / LPR;
    const int c0 = (lane % LPR) * 4;
    const int r0 = warp * RPW + grp * 8;

    float4 acc[8];
    #pragma unroll
    for (int r = 0; r < 8; ++r) acc[r] = make_float4(0.f, 0.f, 0.f, 0.f);

    #pragma unroll 4
    for (int k4 = 0; k4 < 32; ++k4) {
        float4 w0 = *(const float4*)&shW[(4 * k4 + 0) * NC + c0];
        float4 w1 = *(const float4*)&shW[(4 * k4 + 1) * NC + c0];
        float4 w2 = *(const float4*)&shW[(4 * k4 + 2) * NC + c0];
        float4 w3 = *(const float4*)&shW[(4 * k4 + 3) * NC + c0];
        #pragma unroll
        for (int r = 0; r < 8; ++r) {
            float4 xv = *(const float4*)&shX[(r0 + r) * 128 + 4 * k4];
            acc[r].x += xv.x * w0.x + xv.y * w1.x + xv.z * w2.x + xv.w * w3.x;
            acc[r].y += xv.x * w0.y + xv.y * w1.y + xv.z * w2.y + xv.w * w3.y;
            acc[r].z += xv.x * w0.z + xv.y * w1.z + xv.z * w2.z + xv.w * w3.z;
            acc[r].w += xv.x * w0.w + xv.y * w1.w + xv.z * w2.w + xv.w * w3.w;
        }
    }

    #pragma unroll
    for (int r = 0; r < 8; ++r) {
        int gr = rowBase + r0 + r;
        if (gr < M) {
            float di = g_dinv[gr];
            float4 v = acc[r];
            v.x *= di; v.y *= di; v.z *= di; v.w *= di;
            *(float4*)&H[(size_t)gr * NC + c0] = v;
        }
    }
}

// ---------------------------------------------------------------------------
// Gather (CSR): out[d] = [relu]( dinv[d] * (h'[d] + sum_{s in N(d)} h'[s]) + b )
// One warp per dst row. C=128: float4/lane. Cooperative src-index loads + shfl.
// ---------------------------------------------------------------------------
template <bool RELU>
__global__ void gather128_kernel(const float* __restrict__ Hs, const float* __restrict__ b,
                                 float* __restrict__ out, int M) {
    int row = (blockIdx.x * blockDim.x + threadIdx.x) >> 5;
    int lane = threadIdx.x & 31;
    if (row >= M) return;
    int p0 = __ldg(&g_row_ptr[row]);
    int p1 = __ldg(&g_row_ptr[row + 1]);
    float4 acc = __ldg((const float4*)&Hs[(size_t)row * 128 + lane * 4]);   // self loop
    for (int base = p0; base < p1; base += 32) {
        int pl = base + lane;
        int s_l = (pl < p1) ? __ldg(&g_csr_src[pl]) : 0;
        int n = min(32, p1 - base);
        int k = 0;
        for (; k + 4 <= n; k += 4) {
            int s0 = __shfl_sync(0xffffffffu, s_l, k);
            int s1 = __shfl_sync(0xffffffffu, s_l, k + 1);
            int s2 = __shfl_sync(0xffffffffu, s_l, k + 2);
            int s3 = __shfl_sync(0xffffffffu, s_l, k + 3);
            float4 v0 = __ldg((const float4*)&Hs[(size_t)s0 * 128 + lane * 4]);
            float4 v1 = __ldg((const float4*)&Hs[(size_t)s1 * 128 + lane * 4]);
            float4 v2 = __ldg((const float4*)&Hs[(size_t)s2 * 128 + lane * 4]);
            float4 v3 = __ldg((const float4*)&Hs[(size_t)s3 * 128 + lane * 4]);
            acc.x += (v0.x + v1.x) + (v2.x + v3.x);
            acc.y += (v0.y + v1.y) + (v2.y + v3.y);
            acc.z += (v0.z + v1.z) + (v2.z + v3.z);
            acc.w += (v0.w + v1.w) + (v2.w + v3.w);
        }
        for (; k < n; ++k) {
            int s = __shfl_sync(0xffffffffu, s_l, k);
            float4 v = __ldg((const float4*)&Hs[(size_t)s * 128 + lane * 4]);
            acc.x += v.x; acc.y += v.y; acc.z += v.z; acc.w += v.w;
        }
    }
    float di = __ldg(&g_dinv[row]);
    float4 bv = __ldg((const float4*)&b[lane * 4]);
    float4 o;
    o.x = acc.x * di + bv.x;
    o.y = acc.y * di + bv.y;
    o.z = acc.z * di + bv.z;
    o.w = acc.w * di + bv.w;
    if (RELU) {
        o.x = fmaxf(o.x, 0.f); o.y = fmaxf(o.y, 0.f);
        o.z = fmaxf(o.z, 0.f); o.w = fmaxf(o.w, 0.f);
    }
    *(float4*)&out[(size_t)row * 128 + lane * 4] = o;
}

template <bool RELU>
__global__ void gather64_kernel(const float* __restrict__ Hs, const float* __restrict__ b,
                                float* __restrict__ out, int M) {
    int row = (blockIdx.x * blockDim.x + threadIdx.x) >> 5;
    int lane = threadIdx.x & 31;
    if (row >= M) return;
    int p0 = __ldg(&g_row_ptr[row]);
    int p1 = __ldg(&g_row_ptr[row + 1]);
    float2 acc = __ldg((const float2*)&Hs[(size_t)row * 64 + lane * 2]);    // self loop
    for (int base = p0; base < p1; base += 32) {
        int pl = base + lane;
        int s_l = (pl < p1) ? __ldg(&g_csr_src[pl]) : 0;
        int n = min(32, p1 - base);
        int k = 0;
        for (; k + 4 <= n; k += 4) {
            int s0 = __shfl_sync(0xffffffffu, s_l, k);
            int s1 = __shfl_sync(0xffffffffu, s_l, k + 1);
            int s2 = __shfl_sync(0xffffffffu, s_l, k + 2);
            int s3 = __shfl_sync(0xffffffffu, s_l, k + 3);
            float2 v0 = __ldg((const float2*)&Hs[(size_t)s0 * 64 + lane * 2]);
            float2 v1 = __ldg((const float2*)&Hs[(size_t)s1 * 64 + lane * 2]);
            float2 v2 = __ldg((const float2*)&Hs[(size_t)s2 * 64 + lane * 2]);
            float2 v3 = __ldg((const float2*)&Hs[(size_t)s3 * 64 + lane * 2]);
            acc.x += (v0.x + v1.x) + (v2.x + v3.x);
            acc.y += (v0.y + v1.y) + (v2.y + v3.y);
        }
        for (; k < n; ++k) {
            int s = __shfl_sync(0xffffffffu, s_l, k);
            float2 v = __ldg((const float2*)&Hs[(size_t)s * 64 + lane * 2]);
            acc.x += v.x; acc.y += v.y;
        }
    }
    float di = __ldg(&g_dinv[row]);
    float2 bv = __ldg((const float2*)&b[lane * 2]);
    float2 o;
    o.x = acc.x * di + bv.x;
    o.y = acc.y * di + bv.y;
    if (RELU) { o.x = fmaxf(o.x, 0.f); o.y = fmaxf(o.y, 0.f); }
    *(float2*)&out[(size_t)row * 64 + lane * 2] = o;
}

// ---------------------------------------------------------------------------
// Launch — inputs identified by element-count rank (all counts distinct):
//   x(12.8M) > edge(3.2M) > W1(16384) > W2(8192) > b1(128) > b2(64)
// ---------------------------------------------------------------------------
extern "C" void kernel_launch(void* const* d_in, const int* in_sizes, int n_in,
                              void* d_out, int out_size) {
    int idxs[8];
    for (int i = 0; i < n_in; ++i) idxs[i] = i;
    for (int i = 0; i < n_in; ++i)
        for (int j = i + 1; j < n_in; ++j)
            if (in_sizes[idxs[j]] > in_sizes[idxs[i]]) { int t = idxs[i]; idxs[i] = idxs[j]; idxs[j] = t; }

    const float* x    = (const float*)d_in[idxs[0]];
    const int*   ei32 = (const int*)  d_in[idxs[1]];
    const float* W1   = (const float*)d_in[idxs[2]];
    const float* W2   = (const float*)d_in[idxs[3]];
    const float* b1   = (const float*)d_in[idxs[4]];
    const float* b2   = (const float*)d_in[idxs[5]];
    const int x_elems = in_sizes[idxs[0]];
    const int e_elems = in_sizes[idxs[1]];

    const int M = x_elems / 128;   // 100000
    const int E = e_elems / 2;     // 1600000
    const int NB = (M + SCAN_BLK - 1) / SCAN_BLK;

    void *p_degi, *p_h, *p_y;
    cudaGetSymbolAddress(&p_degi, g_degi);
    cudaGetSymbolAddress(&p_h,    g_h);
    cudaGetSymbolAddress(&p_y,    g_y);

    constexpr int SMEM = 98304;
    cudaFuncSetAttribute(gemm_kernel<128>, cudaFuncAttributeMaxDynamicSharedMemorySize, SMEM);
    cudaFuncSetAttribute(gemm_kernel<64>,  cudaFuncAttributeMaxDynamicSharedMemorySize, SMEM);

    // CSR build (recomputed every call; deterministic up to fp add order)
    detect_dtype_kernel<<<1, 32>>>(ei32, e_elems);
    cudaMemsetAsync(p_degi, 0, (size_t)M * sizeof(int));
    count_deg_kernel<<<(E + 255) / 256, 256>>>(ei32, E, M);
    dinv_kernel<<<(M + 255) / 256, 256>>>(M);
    scan1_kernel<<<NB, SCAN_BLK>>>(M);
    scan2_kernel<<<1, 32>>>(NB);
    scan3_kernel<<<(M + 255) / 256, 256>>>(M);
    fill_csr_kernel<<<(E + 255) / 256, 256>>>(ei32, E, M);

    // ---- Layer 1: h1' = (x@W1)*dinv ; y = relu(dinv*(sum + self) + b1) ----
    gemm_kernel<128><<<(M + 63) / 64, 256, SMEM>>>(x, W1, (float*)p_h, M);
    gather128_kernel<true><<<(M * 32 + 255) / 256, 256>>>(
        (const float*)p_h, b1, (float*)p_y, M);

    // ---- Layer 2: h2' = (y@W2)*dinv ; out = dinv*(sum + self) + b2 ----
    gemm_kernel<64><<<(M + 127) / 128, 256, SMEM>>>((const float*)p_y, W2, (float*)p_h, M);
    gather64_kernel<false><<<(M * 32 + 255) / 256, 256>>>(
        (const float*)p_h, b2, (float*)d_out, M);
}

// round 8
// speedup vs baseline: 1.7215x; 1.0474x over previous
#include <cuda_runtime.h>
#include <cstdint>

#define MAX_NODES 100000
#define MAX_EDGES 1600000
#define SCAN_BLK 1024

// Scratch (allocation-free device globals); 256B-aligned for float4 access.
__device__ __align__(256) float g_h[(size_t)MAX_NODES * 128];   // h = X@W (unscaled)
__device__ __align__(256) float g_y[(size_t)MAX_NODES * 128];   // layer-1 output
__device__ __align__(256) float g_dinv[MAX_NODES];
__device__ __align__(256) int   g_degi[MAX_NODES];
__device__ __align__(256) int   g_rtmp[MAX_NODES];
__device__ __align__(256) int   g_row_ptr[MAX_NODES + 1];
__device__ __align__(256) int   g_cursor[MAX_NODES];
__device__ __align__(256) int   g_csr_src[MAX_EDGES];
__device__ __align__(256) int   g_bsums[(MAX_NODES + SCAN_BLK - 1) / SCAN_BLK + 1];
__device__ int g_i64;   // 1 if edge_index is int64, 0 if int32

// ---------------------------------------------------------------------------
// Edge dtype detection (1 warp): int64 values < 1e5 have all-zero high words.
// ---------------------------------------------------------------------------
__global__ void detect_dtype_kernel(const int* __restrict__ ei32, int n_elem) {
    int lim = n_elem < 2048 ? n_elem : 2048;
    int acc = 0;
    for (int i = 1 + 2 * threadIdx.x; i < lim; i += 64) acc |= ei32[i];
    acc = __reduce_or_sync(0xffffffffu, acc);
    if (threadIdx.x == 0) g_i64 = (acc == 0) ? 1 : 0;
}

__device__ __forceinline__ int edge_val(const int* __restrict__ ei32, size_t elem, int sh) {
    return ei32[elem << sh];
}

// ---------------------------------------------------------------------------
// CSR build: degree histogram -> exclusive scan -> cursor fill
// ---------------------------------------------------------------------------
__global__ void count_deg_kernel(const int* __restrict__ ei32, int E, int M) {
    int e = blockIdx.x * blockDim.x + threadIdx.x;
    if (e < E) {
        int sh = g_i64;
        int d = edge_val(ei32, (size_t)E + e, sh);
        if ((unsigned)d < (unsigned)M) atomicAdd(&g_degi[d], 1);
    }
}

__global__ void dinv_kernel(int M) {
    int i = blockIdx.x * blockDim.x + threadIdx.x;
    if (i < M) g_dinv[i] = rsqrtf((float)g_degi[i] + 1.0f);  // +1 self loop
}

__global__ void scan1_kernel(int M) {
    __shared__ int sm[SCAN_BLK];
    int i = blockIdx.x * SCAN_BLK + threadIdx.x;
    int v = (i < M) ? g_degi[i] : 0;
    sm[threadIdx.x] = v;
    __syncthreads();
    for (int off = 1; off < SCAN_BLK; off <<= 1) {
        int t = (threadIdx.x >= off) ? sm[threadIdx.x - off] : 0;
        __syncthreads();
        sm[threadIdx.x] += t;
        __syncthreads();
    }
    if (i < M) g_rtmp[i] = sm[threadIdx.x] - v;          // exclusive within block
    if (threadIdx.x == SCAN_BLK - 1) g_bsums[blockIdx.x] = sm[SCAN_BLK - 1];
}

__global__ void scan2_kernel(int nb) {       // nb <= 128: one-block Hillis-Steele
    __shared__ int sm[128];
    int t = threadIdx.x;
    int v = (t < nb) ? g_bsums[t] : 0;
    sm[t] = v;
    __syncthreads();
    for (int off = 1; off < 128; off <<= 1) {
        int u = (t >= off) ? sm[t - off] : 0;
        __syncthreads();
        sm[t] += u;
        __syncthreads();
    }
    if (t < nb) g_bsums[t] = sm[t] - v;      // exclusive
}

__global__ void scan3_kernel(int M) {
    int i = blockIdx.x * blockDim.x + threadIdx.x;
    if (i < M) {
        int rp = g_rtmp[i] + g_bsums[i / SCAN_BLK];
        g_row_ptr[i] = rp;
        g_cursor[i]  = rp;
        if (i == M - 1) g_row_ptr[M] = rp + g_degi[i];
    }
}

__global__ void fill_csr_kernel(const int* __restrict__ ei32, int E, int M) {
    int e = blockIdx.x * blockDim.x + threadIdx.x;
    if (e < E) {
        int sh = g_i64;
        int s = edge_val(ei32, (size_t)e, sh);
        int d = edge_val(ei32, (size_t)E + e, sh);
        if ((unsigned)s < (unsigned)M && (unsigned)d < (unsigned)M) {
            int pos = atomicAdd(&g_cursor[d], 1);
            g_csr_src[pos] = s;
        }
    }
}

// ---------------------------------------------------------------------------
// GEMM: H[M,NC] = X[M,128] @ W[128,NC]   (fp32 SIMT; no dinv — done in gather)
// ---------------------------------------------------------------------------
template <int NC>
__global__ void gemm_kernel(const float* __restrict__ X, const float* __restrict__ W,
                            float* __restrict__ H, int M) {
    extern __shared__ float sh[];
    float* shW = sh;                       // 128*NC floats
    float* shX = sh + 128 * NC;            // ROWS*128 floats
    constexpr int ROWS = (NC == 128) ? 64 : 128;

    const int tid = threadIdx.x;
    const int rowBase = blockIdx.x * ROWS;

    for (int i = tid; i < 128 * NC / 4; i += 256)
        ((float4*)shW)[i] = ((const float4*)W)[i];

    for (int i = tid; i < ROWS * 32; i += 256) {
        int r = i >> 5;
        int gr = rowBase + r;
        float4 v = make_float4(0.f, 0.f, 0.f, 0.f);
        if (gr < M) v = ((const float4*)X)[(size_t)gr * 32 + (i & 31)];
        ((float4*)shX)[i] = v;
    }
    __syncthreads();

    const int warp = tid >> 5, lane = tid & 31;
    constexpr int LPR = NC / 4;
    constexpr int RPW = ROWS / 8;
    const int grp = lane / LPR;
    const int c0 = (lane % LPR) * 4;
    const int r0 = warp * RPW + grp * 8;

    float4 acc[8];
    #pragma unroll
    for (int r = 0; r < 8; ++r) acc[r] = make_float4(0.f, 0.f, 0.f, 0.f);

    #pragma unroll 4
    for (int k4 = 0; k4 < 32; ++k4) {
        float4 w0 = *(const float4*)&shW[(4 * k4 + 0) * NC + c0];
        float4 w1 = *(const float4*)&shW[(4 * k4 + 1) * NC + c0];
        float4 w2 = *(const float4*)&shW[(4 * k4 + 2) * NC + c0];
        float4 w3 = *(const float4*)&shW[(4 * k4 + 3) * NC + c0];
        #pragma unroll
        for (int r = 0; r < 8; ++r) {
            float4 xv = *(const float4*)&shX[(r0 + r) * 128 + 4 * k4];
            acc[r].x += xv.x * w0.x + xv.y * w1.x + xv.z * w2.x + xv.w * w3.x;
            acc[r].y += xv.x * w0.y + xv.y * w1.y + xv.z * w2.y + xv.w * w3.y;
            acc[r].z += xv.x * w0.z + xv.y * w1.z + xv.z * w2.z + xv.w * w3.z;
            acc[r].w += xv.x * w0.w + xv.y * w1.w + xv.z * w2.w + xv.w * w3.w;
        }
    }

    #pragma unroll
    for (int r = 0; r < 8; ++r) {
        int gr = rowBase + r0 + r;
        if (gr < M) *(float4*)&H[(size_t)gr * NC + c0] = acc[r];
    }
}

// ---------------------------------------------------------------------------
// Gather (CSR): out[d] = [relu]( dinv[d]*(h[d]*dinv[d] + sum_s h[s]*dinv[s]) + b )
// One warp per dst row; dinv[s] fetched with the src index and shfl-broadcast.
// ---------------------------------------------------------------------------
template <bool RELU>
__global__ void gather128_kernel(const float* __restrict__ Hs, const float* __restrict__ b,
                                 float* __restrict__ out, int M) {
    int row = (blockIdx.x * blockDim.x + threadIdx.x) >> 5;
    int lane = threadIdx.x & 31;
    if (row >= M) return;
    int p0 = __ldg(&g_row_ptr[row]);
    int p1 = __ldg(&g_row_ptr[row + 1]);
    float di = __ldg(&g_dinv[row]);
    float4 acc = __ldg((const float4*)&Hs[(size_t)row * 128 + lane * 4]);   // self loop
    acc.x *= di; acc.y *= di; acc.z *= di; acc.w *= di;
    for (int base = p0; base < p1; base += 32) {
        int pl = base + lane;
        int s_l = 0; float dl = 0.f;
        if (pl < p1) { s_l = __ldg(&g_csr_src[pl]); dl = __ldg(&g_dinv[s_l]); }
        int n = min(32, p1 - base);
        int k = 0;
        for (; k + 4 <= n; k += 4) {
            int s0 = __shfl_sync(0xffffffffu, s_l, k);
            int s1 = __shfl_sync(0xffffffffu, s_l, k + 1);
            int s2 = __shfl_sync(0xffffffffu, s_l, k + 2);
            int s3 = __shfl_sync(0xffffffffu, s_l, k + 3);
            float d0 = __shfl_sync(0xffffffffu, dl, k);
            float d1 = __shfl_sync(0xffffffffu, dl, k + 1);
            float d2 = __shfl_sync(0xffffffffu, dl, k + 2);
            float d3 = __shfl_sync(0xffffffffu, dl, k + 3);
            float4 v0 = __ldg((const float4*)&Hs[(size_t)s0 * 128 + lane * 4]);
            float4 v1 = __ldg((const float4*)&Hs[(size_t)s1 * 128 + lane * 4]);
            float4 v2 = __ldg((const float4*)&Hs[(size_t)s2 * 128 + lane * 4]);
            float4 v3 = __ldg((const float4*)&Hs[(size_t)s3 * 128 + lane * 4]);
            acc.x += v0.x * d0 + v1.x * d1 + v2.x * d2 + v3.x * d3;
            acc.y += v0.y * d0 + v1.y * d1 + v2.y * d2 + v3.y * d3;
            acc.z += v0.z * d0 + v1.z * d1 + v2.z * d2 + v3.z * d3;
            acc.w += v0.w * d0 + v1.w * d1 + v2.w * d2 + v3.w * d3;
        }
        for (; k < n; ++k) {
            int s = __shfl_sync(0xffffffffu, s_l, k);
            float d = __shfl_sync(0xffffffffu, dl, k);
            float4 v = __ldg((const float4*)&Hs[(size_t)s * 128 + lane * 4]);
            acc.x += v.x * d; acc.y += v.y * d; acc.z += v.z * d; acc.w += v.w * d;
        }
    }
    float4 bv = __ldg((const float4*)&b[lane * 4]);
    float4 o;
    o.x = acc.x * di + bv.x;
    o.y = acc.y * di + bv.y;
    o.z = acc.z * di + bv.z;
    o.w = acc.w * di + bv.w;
    if (RELU) {
        o.x = fmaxf(o.x, 0.f); o.y = fmaxf(o.y, 0.f);
        o.z = fmaxf(o.z, 0.f); o.w = fmaxf(o.w, 0.f);
    }
    *(float4*)&out[(size_t)row * 128 + lane * 4] = o;
}

template <bool RELU>
__global__ void gather64_kernel(const float* __restrict__ Hs, const float* __restrict__ b,
                                float* __restrict__ out, int M) {
    int row = (blockIdx.x * blockDim.x + threadIdx.x) >> 5;
    int lane = threadIdx.x & 31;
    if (row >= M) return;
    int p0 = __ldg(&g_row_ptr[row]);
    int p1 = __ldg(&g_row_ptr[row + 1]);
    float di = __ldg(&g_dinv[row]);
    float2 acc = __ldg((const float2*)&Hs[(size_t)row * 64 + lane * 2]);    // self loop
    acc.x *= di; acc.y *= di;
    for (int base = p0; base < p1; base += 32) {
        int pl = base + lane;
        int s_l = 0; float dl = 0.f;
        if (pl < p1) { s_l = __ldg(&g_csr_src[pl]); dl = __ldg(&g_dinv[s_l]); }
        int n = min(32, p1 - base);
        int k = 0;
        for (; k + 4 <= n; k += 4) {
            int s0 = __shfl_sync(0xffffffffu, s_l, k);
            int s1 = __shfl_sync(0xffffffffu, s_l, k + 1);
            int s2 = __shfl_sync(0xffffffffu, s_l, k + 2);
            int s3 = __shfl_sync(0xffffffffu, s_l, k + 3);
            float d0 = __shfl_sync(0xffffffffu, dl, k);
            float d1 = __shfl_sync(0xffffffffu, dl, k + 1);
            float d2 = __shfl_sync(0xffffffffu, dl, k + 2);
            float d3 = __shfl_sync(0xffffffffu, dl, k + 3);
            float2 v0 = __ldg((const float2*)&Hs[(size_t)s0 * 64 + lane * 2]);
            float2 v1 = __ldg((const float2*)&Hs[(size_t)s1 * 64 + lane * 2]);
            float2 v2 = __ldg((const float2*)&Hs[(size_t)s2 * 64 + lane * 2]);
            float2 v3 = __ldg((const float2*)&Hs[(size_t)s3 * 64 + lane * 2]);
            acc.x += v0.x * d0 + v1.x * d1 + v2.x * d2 + v3.x * d3;
            acc.y += v0.y * d0 + v1.y * d1 + v2.y * d2 + v3.y * d3;
        }
        for (; k < n; ++k) {
            int s = __shfl_sync(0xffffffffu, s_l, k);
            float d = __shfl_sync(0xffffffffu, dl, k);
            float2 v = __ldg((const float2*)&Hs[(size_t)s * 64 + lane * 2]);
            acc.x += v.x * d; acc.y += v.y * d;
        }
    }
    float2 bv = __ldg((const float2*)&b[lane * 2]);
    float2 o;
    o.x = acc.x * di + bv.x;
    o.y = acc.y * di + bv.y;
    if (RELU) { o.x = fmaxf(o.x, 0.f); o.y = fmaxf(o.y, 0.f); }
    *(float2*)&out[(size_t)row * 64 + lane * 2] = o;
}

// ---------------------------------------------------------------------------
// Launch — size-rank input identification; CSR chain forked to a side stream
// and overlapped with gemm128 (which no longer depends on dinv).
// ---------------------------------------------------------------------------
extern "C" void kernel_launch(void* const* d_in, const int* in_sizes, int n_in,
                              void* d_out, int out_size) {
    int idxs[8];
    for (int i = 0; i < n_in; ++i) idxs[i] = i;
    for (int i = 0; i < n_in; ++i)
        for (int j = i + 1; j < n_in; ++j)
            if (in_sizes[idxs[j]] > in_sizes[idxs[i]]) { int t = idxs[i]; idxs[i] = idxs[j]; idxs[j] = t; }

    const float* x    = (const float*)d_in[idxs[0]];
    const int*   ei32 = (const int*)  d_in[idxs[1]];
    const float* W1   = (const float*)d_in[idxs[2]];
    const float* W2   = (const float*)d_in[idxs[3]];
    const float* b1   = (const float*)d_in[idxs[4]];
    const float* b2   = (const float*)d_in[idxs[5]];
    const int x_elems = in_sizes[idxs[0]];
    const int e_elems = in_sizes[idxs[1]];

    const int M = x_elems / 128;   // 100000
    const int E = e_elems / 2;     // 1600000
    const int NB = (M + SCAN_BLK - 1) / SCAN_BLK;

    void *p_degi, *p_h, *p_y;
    cudaGetSymbolAddress(&p_degi, g_degi);
    cudaGetSymbolAddress(&p_h,    g_h);
    cudaGetSymbolAddress(&p_y,    g_y);

    constexpr int SMEM = 98304;
    cudaFuncSetAttribute(gemm_kernel<128>, cudaFuncAttributeMaxDynamicSharedMemorySize, SMEM);
    cudaFuncSetAttribute(gemm_kernel<64>,  cudaFuncAttributeMaxDynamicSharedMemorySize, SMEM);

    // One-time host resources (no device memory involved).
    static cudaStream_t sB = nullptr;
    static cudaEvent_t evF = nullptr, evJ = nullptr;
    if (!sB) {
        cudaStreamCreateWithFlags(&sB, cudaStreamNonBlocking);
        cudaEventCreateWithFlags(&evF, cudaEventDisableTiming);
        cudaEventCreateWithFlags(&evJ, cudaEventDisableTiming);
    }

    // Fork: CSR chain on side stream sB.
    cudaEventRecord(evF, 0);
    cudaStreamWaitEvent(sB, evF, 0);
    detect_dtype_kernel<<<1, 32, 0, sB>>>(ei32, e_elems);
    cudaMemsetAsync(p_degi, 0, (size_t)M * sizeof(int), sB);
    count_deg_kernel<<<(E + 255) / 256, 256, 0, sB>>>(ei32, E, M);
    dinv_kernel<<<(M + 255) / 256, 256, 0, sB>>>(M);
    scan1_kernel<<<NB, SCAN_BLK, 0, sB>>>(M);
    scan2_kernel<<<1, 128, 0, sB>>>(NB);
    scan3_kernel<<<(M + 255) / 256, 256, 0, sB>>>(M);
    fill_csr_kernel<<<(E + 255) / 256, 256, 0, sB>>>(ei32, E, M);
    cudaEventRecord(evJ, sB);

    // Concurrent: layer-1 GEMM on the main stream (independent of CSR/dinv).
    gemm_kernel<128><<<(M + 63) / 64, 256, SMEM>>>(x, W1, (float*)p_h, M);

    // Join, then the dependent chain.
    cudaStreamWaitEvent(0, evJ, 0);
    gather128_kernel<true><<<(M * 32 + 255) / 256, 256>>>(
        (const float*)p_h, b1, (float*)p_y, M);
    gemm_kernel<64><<<(M + 127) / 128, 256, SMEM>>>((const float*)p_y, W2, (float*)p_h, M);
    gather64_kernel<false><<<(M * 32 + 255) / 256, 256>>>(
        (const float*)p_h, b2, (float*)d_out, M);
}

// round 9
// speedup vs baseline: 1.8277x; 1.0616x over previous
#include <cuda_runtime.h>
#include <cstdint>

#define MAX_NODES 100000
#define MAX_EDGES 1600000
#define SCAN_BLK 1024

typedef unsigned long long u64;

// Scratch (allocation-free device globals); 256B-aligned for float4 access.
__device__ __align__(256) float g_h[(size_t)MAX_NODES * 128];   // h = X@W (unscaled)
__device__ __align__(256) float g_y[(size_t)MAX_NODES * 128];   // layer-1 output
__device__ __align__(256) float g_dinv[MAX_NODES];
__device__ __align__(256) int   g_degi[MAX_NODES];
__device__ __align__(256) int   g_rtmp[MAX_NODES];
__device__ __align__(256) int   g_row_ptr[MAX_NODES + 1];
__device__ __align__(256) int   g_cursor[MAX_NODES];
__device__ __align__(256) int   g_csr_src[MAX_EDGES];
__device__ __align__(256) int   g_bsums[(MAX_NODES + SCAN_BLK - 1) / SCAN_BLK + 1];
__device__ int g_i64;   // 1 if edge_index is int64, 0 if int32

// ---------------------------------------------------------------------------
// Edge dtype detection (1 warp): int64 values < 1e5 have all-zero high words.
// ---------------------------------------------------------------------------
__global__ void detect_dtype_kernel(const int* __restrict__ ei32, int n_elem) {
    int lim = n_elem < 2048 ? n_elem : 2048;
    int acc = 0;
    for (int i = 1 + 2 * threadIdx.x; i < lim; i += 64) acc |= ei32[i];
    acc = __reduce_or_sync(0xffffffffu, acc);
    if (threadIdx.x == 0) g_i64 = (acc == 0) ? 1 : 0;
}

__device__ __forceinline__ int edge_val(const int* __restrict__ ei32, size_t elem, int sh) {
    return ei32[elem << sh];
}

// ---------------------------------------------------------------------------
// CSR build: degree histogram -> exclusive scan -> cursor fill
// ---------------------------------------------------------------------------
__global__ void count_deg_kernel(const int* __restrict__ ei32, int E, int M) {
    int e = blockIdx.x * blockDim.x + threadIdx.x;
    if (e < E) {
        int sh = g_i64;
        int d = edge_val(ei32, (size_t)E + e, sh);
        if ((unsigned)d < (unsigned)M) atomicAdd(&g_degi[d], 1);
    }
}

__global__ void dinv_kernel(int M) {
    int i = blockIdx.x * blockDim.x + threadIdx.x;
    if (i < M) g_dinv[i] = rsqrtf((float)g_degi[i] + 1.0f);  // +1 self loop
}

__global__ void scan1_kernel(int M) {
    __shared__ int sm[SCAN_BLK];
    int i = blockIdx.x * SCAN_BLK + threadIdx.x;
    int v = (i < M) ? g_degi[i] : 0;
    sm[threadIdx.x] = v;
    __syncthreads();
    for (int off = 1; off < SCAN_BLK; off <<= 1) {
        int t = (threadIdx.x >= off) ? sm[threadIdx.x - off] : 0;
        __syncthreads();
        sm[threadIdx.x] += t;
        __syncthreads();
    }
    if (i < M) g_rtmp[i] = sm[threadIdx.x] - v;          // exclusive within block
    if (threadIdx.x == SCAN_BLK - 1) g_bsums[blockIdx.x] = sm[SCAN_BLK - 1];
}

__global__ void scan2_kernel(int nb) {       // nb <= 128: one-block Hillis-Steele
    __shared__ int sm[128];
    int t = threadIdx.x;
    int v = (t < nb) ? g_bsums[t] : 0;
    sm[t] = v;
    __syncthreads();
    for (int off = 1; off < 128; off <<= 1) {
        int u = (t >= off) ? sm[t - off] : 0;
        __syncthreads();
        sm[t] += u;
        __syncthreads();
    }
    if (t < nb) g_bsums[t] = sm[t] - v;      // exclusive
}

__global__ void scan3_kernel(int M) {
    int i = blockIdx.x * blockDim.x + threadIdx.x;
    if (i < M) {
        int rp = g_rtmp[i] + g_bsums[i / SCAN_BLK];
        g_row_ptr[i] = rp;
        g_cursor[i]  = rp;
        if (i == M - 1) g_row_ptr[M] = rp + g_degi[i];
    }
}

__global__ void fill_csr_kernel(const int* __restrict__ ei32, int E, int M) {
    int e = blockIdx.x * blockDim.x + threadIdx.x;
    if (e < E) {
        int sh = g_i64;
        int s = edge_val(ei32, (size_t)e, sh);
        int d = edge_val(ei32, (size_t)E + e, sh);
        if ((unsigned)s < (unsigned)M && (unsigned)d < (unsigned)M) {
            int pos = atomicAdd(&g_cursor[d], 1);
            g_csr_src[pos] = s;
        }
    }
}

// ---------------------------------------------------------------------------
// GEMM: H[M,NC] = X[M,128] @ W[128,NC] using packed fma.rn.f32x2.
// Pairs packed along K (even/odd partial sums, merged at the end):
//   x2 = (x[k], x[k+1])  — contiguous LDS.64 from shX (warp-broadcast)
//   w2 = (w[k][c], w[k+1][c]) — contiguous LDS.64 from transposed shWt[c][k]
// shWt row stride 130 floats keeps conflicts at 2-way.
// ---------------------------------------------------------------------------
__device__ __forceinline__ void fma2(u64& d, u64 a, u64 b) {
    asm("fma.rn.f32x2 %0, %1, %2, %0;" : "+l"(d) : "l"(a), "l"(b));
}

template <int NC>
__global__ void __launch_bounds__(256) gemm_kernel(
        const float* __restrict__ X, const float* __restrict__ W,
        float* __restrict__ H, int M) {
    constexpr int WSTRIDE = 130;           // padded floats per channel row
    extern __shared__ float sh[];
    float* shWt = sh;                      // NC * WSTRIDE floats (transposed W)
    float* shX  = sh + NC * WSTRIDE;       // ROWS * 128 floats
    constexpr int ROWS = (NC == 128) ? 64 : 128;

    const int tid = threadIdx.x;
    const int rowBase = blockIdx.x * ROWS;

    // Stage W transposed: shWt[c][k] = W[k][c]
    for (int i = tid; i < 128 * NC; i += 256) {
        int k = i / NC, c = i % NC;
        shWt[c * WSTRIDE + k] = W[i];
    }

    // Stage X tile (row-major, 128 floats per row)
    for (int i = tid; i < ROWS * 32; i += 256) {
        int r = i >> 5;
        int gr = rowBase + r;
        float4 v = make_float4(0.f, 0.f, 0.f, 0.f);
        if (gr < M) v = ((const float4*)X)[(size_t)gr * 32 + (i & 31)];
        ((float4*)shX)[i] = v;
    }
    __syncthreads();

    const int warp = tid >> 5, lane = tid & 31;
    constexpr int CGRP = (NC == 128) ? 32 : 16;  // lanes covering the channels
    const int lc  = lane % CGRP;                 // channel within group
    const int grp = lane / CGRP;                 // 0, or 0/1 for NC==64
    constexpr int RPW = ROWS / 8;                // rows per warp
    const int r0 = warp * RPW + grp * 8;

    u64 acc[8][4];
    #pragma unroll
    for (int r = 0; r < 8; ++r)
        #pragma unroll
        for (int j = 0; j < 4; ++j) acc[r][j] = 0ULL;

    const float* wbase = &shWt[lc * WSTRIDE];

    #pragma unroll 4
    for (int k2 = 0; k2 < 64; ++k2) {
        u64 w2[4];
        #pragma unroll
        for (int j = 0; j < 4; ++j)
            w2[j] = *(const u64*)&wbase[j * (CGRP * WSTRIDE) + 2 * k2];
        #pragma unroll
        for (int r = 0; r < 8; ++r) {
            u64 x2 = *(const u64*)&shX[(r0 + r) * 128 + 2 * k2];
            fma2(acc[r][0], x2, w2[0]);
            fma2(acc[r][1], x2, w2[1]);
            fma2(acc[r][2], x2, w2[2]);
            fma2(acc[r][3], x2, w2[3]);
        }
    }

    #pragma unroll
    for (int r = 0; r < 8; ++r) {
        int gr = rowBase + r0 + r;
        if (gr < M) {
            #pragma unroll
            for (int j = 0; j < 4; ++j) {
                u64 a = acc[r][j];
                float lo = __uint_as_float((unsigned)(a & 0xffffffffULL));
                float hi = __uint_as_float((unsigned)(a >> 32));
                H[(size_t)gr * NC + lc + CGRP * j] = lo + hi;
            }
        }
    }
}

// ---------------------------------------------------------------------------
// Gather (CSR): out[d] = [relu]( dinv[d]*(h[d]*dinv[d] + sum_s h[s]*dinv[s]) + b )
// ---------------------------------------------------------------------------
template <bool RELU>
__global__ void gather128_kernel(const float* __restrict__ Hs, const float* __restrict__ b,
                                 float* __restrict__ out, int M) {
    int row = (blockIdx.x * blockDim.x + threadIdx.x) >> 5;
    int lane = threadIdx.x & 31;
    if (row >= M) return;
    int p0 = __ldg(&g_row_ptr[row]);
    int p1 = __ldg(&g_row_ptr[row + 1]);
    float di = __ldg(&g_dinv[row]);
    float4 acc = __ldg((const float4*)&Hs[(size_t)row * 128 + lane * 4]);   // self loop
    acc.x *= di; acc.y *= di; acc.z *= di; acc.w *= di;
    for (int base = p0; base < p1; base += 32) {
        int pl = base + lane;
        int s_l = 0; float dl = 0.f;
        if (pl < p1) { s_l = __ldg(&g_csr_src[pl]); dl = __ldg(&g_dinv[s_l]); }
        int n = min(32, p1 - base);
        int k = 0;
        for (; k + 4 <= n; k += 4) {
            int s0 = __shfl_sync(0xffffffffu, s_l, k);
            int s1 = __shfl_sync(0xffffffffu, s_l, k + 1);
            int s2 = __shfl_sync(0xffffffffu, s_l, k + 2);
            int s3 = __shfl_sync(0xffffffffu, s_l, k + 3);
            float d0 = __shfl_sync(0xffffffffu, dl, k);
            float d1 = __shfl_sync(0xffffffffu, dl, k + 1);
            float d2 = __shfl_sync(0xffffffffu, dl, k + 2);
            float d3 = __shfl_sync(0xffffffffu, dl, k + 3);
            float4 v0 = __ldg((const float4*)&Hs[(size_t)s0 * 128 + lane * 4]);
            float4 v1 = __ldg((const float4*)&Hs[(size_t)s1 * 128 + lane * 4]);
            float4 v2 = __ldg((const float4*)&Hs[(size_t)s2 * 128 + lane * 4]);
            float4 v3 = __ldg((const float4*)&Hs[(size_t)s3 * 128 + lane * 4]);
            acc.x += v0.x * d0 + v1.x * d1 + v2.x * d2 + v3.x * d3;
            acc.y += v0.y * d0 + v1.y * d1 + v2.y * d2 + v3.y * d3;
            acc.z += v0.z * d0 + v1.z * d1 + v2.z * d2 + v3.z * d3;
            acc.w += v0.w * d0 + v1.w * d1 + v2.w * d2 + v3.w * d3;
        }
        for (; k < n; ++k) {
            int s = __shfl_sync(0xffffffffu, s_l, k);
            float d = __shfl_sync(0xffffffffu, dl, k);
            float4 v = __ldg((const float4*)&Hs[(size_t)s * 128 + lane * 4]);
            acc.x += v.x * d; acc.y += v.y * d; acc.z += v.z * d; acc.w += v.w * d;
        }
    }
    float4 bv = __ldg((const float4*)&b[lane * 4]);
    float4 o;
    o.x = acc.x * di + bv.x;
    o.y = acc.y * di + bv.y;
    o.z = acc.z * di + bv.z;
    o.w = acc.w * di + bv.w;
    if (RELU) {
        o.x = fmaxf(o.x, 0.f); o.y = fmaxf(o.y, 0.f);
        o.z = fmaxf(o.z, 0.f); o.w = fmaxf(o.w, 0.f);
    }
    *(float4*)&out[(size_t)row * 128 + lane * 4] = o;
}

template <bool RELU>
__global__ void gather64_kernel(const float* __restrict__ Hs, const float* __restrict__ b,
                                float* __restrict__ out, int M) {
    int row = (blockIdx.x * blockDim.x + threadIdx.x) >> 5;
    int lane = threadIdx.x & 31;
    if (row >= M) return;
    int p0 = __ldg(&g_row_ptr[row]);
    int p1 = __ldg(&g_row_ptr[row + 1]);
    float di = __ldg(&g_dinv[row]);
    float2 acc = __ldg((const float2*)&Hs[(size_t)row * 64 + lane * 2]);    // self loop
    acc.x *= di; acc.y *= di;
    for (int base = p0; base < p1; base += 32) {
        int pl = base + lane;
        int s_l = 0; float dl = 0.f;
        if (pl < p1) { s_l = __ldg(&g_csr_src[pl]); dl = __ldg(&g_dinv[s_l]); }
        int n = min(32, p1 - base);
        int k = 0;
        for (; k + 4 <= n; k += 4) {
            int s0 = __shfl_sync(0xffffffffu, s_l, k);
            int s1 = __shfl_sync(0xffffffffu, s_l, k + 1);
            int s2 = __shfl_sync(0xffffffffu, s_l, k + 2);
            int s3 = __shfl_sync(0xffffffffu, s_l, k + 3);
            float d0 = __shfl_sync(0xffffffffu, dl, k);
            float d1 = __shfl_sync(0xffffffffu, dl, k + 1);
            float d2 = __shfl_sync(0xffffffffu, dl, k + 2);
            float d3 = __shfl_sync(0xffffffffu, dl, k + 3);
            float2 v0 = __ldg((const float2*)&Hs[(size_t)s0 * 64 + lane * 2]);
            float2 v1 = __ldg((const float2*)&Hs[(size_t)s1 * 64 + lane * 2]);
            float2 v2 = __ldg((const float2*)&Hs[(size_t)s2 * 64 + lane * 2]);
            float2 v3 = __ldg((const float2*)&Hs[(size_t)s3 * 64 + lane * 2]);
            acc.x += v0.x * d0 + v1.x * d1 + v2.x * d2 + v3.x * d3;
            acc.y += v0.y * d0 + v1.y * d1 + v2.y * d2 + v3.y * d3;
        }
        for (; k < n; ++k) {
            int s = __shfl_sync(0xffffffffu, s_l, k);
            float d = __shfl_sync(0xffffffffu, dl, k);
            float2 v = __ldg((const float2*)&Hs[(size_t)s * 64 + lane * 2]);
            acc.x += v.x * d; acc.y += v.y * d;
        }
    }
    float2 bv = __ldg((const float2*)&b[lane * 2]);
    float2 o;
    o.x = acc.x * di + bv.x;
    o.y = acc.y * di + bv.y;
    if (RELU) { o.x = fmaxf(o.x, 0.f); o.y = fmaxf(o.y, 0.f); }
    *(float2*)&out[(size_t)row * 64 + lane * 2] = o;
}

// ---------------------------------------------------------------------------
// Launch — size-rank input identification; CSR chain forked to a side stream
// and overlapped with gemm128.
// ---------------------------------------------------------------------------
extern "C" void kernel_launch(void* const* d_in, const int* in_sizes, int n_in,
                              void* d_out, int out_size) {
    int idxs[8];
    for (int i = 0; i < n_in; ++i) idxs[i] = i;
    for (int i = 0; i < n_in; ++i)
        for (int j = i + 1; j < n_in; ++j)
            if (in_sizes[idxs[j]] > in_sizes[idxs[i]]) { int t = idxs[i]; idxs[i] = idxs[j]; idxs[j] = t; }

    const float* x    = (const float*)d_in[idxs[0]];
    const int*   ei32 = (const int*)  d_in[idxs[1]];
    const float* W1   = (const float*)d_in[idxs[2]];
    const float* W2   = (const float*)d_in[idxs[3]];
    const float* b1   = (const float*)d_in[idxs[4]];
    const float* b2   = (const float*)d_in[idxs[5]];
    const int x_elems = in_sizes[idxs[0]];
    const int e_elems = in_sizes[idxs[1]];

    const int M = x_elems / 128;   // 100000
    const int E = e_elems / 2;     // 1600000
    const int NB = (M + SCAN_BLK - 1) / SCAN_BLK;

    void *p_degi, *p_h, *p_y;
    cudaGetSymbolAddress(&p_degi, g_degi);
    cudaGetSymbolAddress(&p_h,    g_h);
    cudaGetSymbolAddress(&p_y,    g_y);

    // smem: NC*130 (transposed W, padded) + ROWS*128 (X tile), in floats
    const int SMEM128 = (128 * 130 + 64 * 128) * 4;   // 99,328 B
    const int SMEM64  = (64 * 130 + 128 * 128) * 4;   // 98,816 B
    cudaFuncSetAttribute(gemm_kernel<128>, cudaFuncAttributeMaxDynamicSharedMemorySize, SMEM128);
    cudaFuncSetAttribute(gemm_kernel<64>,  cudaFuncAttributeMaxDynamicSharedMemorySize, SMEM64);

    // One-time host resources (no device memory involved).
    static cudaStream_t sB = nullptr;
    static cudaEvent_t evF = nullptr, evJ = nullptr;
    if (!sB) {
        cudaStreamCreateWithFlags(&sB, cudaStreamNonBlocking);
        cudaEventCreateWithFlags(&evF, cudaEventDisableTiming);
        cudaEventCreateWithFlags(&evJ, cudaEventDisableTiming);
    }

    // Fork: CSR chain on side stream sB.
    cudaEventRecord(evF, 0);
    cudaStreamWaitEvent(sB, evF, 0);
    detect_dtype_kernel<<<1, 32, 0, sB>>>(ei32, e_elems);
    cudaMemsetAsync(p_degi, 0, (size_t)M * sizeof(int), sB);
    count_deg_kernel<<<(E + 255) / 256, 256, 0, sB>>>(ei32, E, M);
    dinv_kernel<<<(M + 255) / 256, 256, 0, sB>>>(M);
    scan1_kernel<<<NB, SCAN_BLK, 0, sB>>>(M);
    scan2_kernel<<<1, 128, 0, sB>>>(NB);
    scan3_kernel<<<(M + 255) / 256, 256, 0, sB>>>(M);
    fill_csr_kernel<<<(E + 255) / 256, 256, 0, sB>>>(ei32, E, M);
    cudaEventRecord(evJ, sB);

    // Concurrent: layer-1 GEMM on the main stream (independent of CSR/dinv).
    gemm_kernel<128><<<(M + 63) / 64, 256, SMEM128>>>(x, W1, (float*)p_h, M);

    // Join, then the dependent chain.
    cudaStreamWaitEvent(0, evJ, 0);
    gather128_kernel<true><<<(M * 32 + 255) / 256, 256>>>(
        (const float*)p_h, b1, (float*)p_y, M);
    gemm_kernel<64><<<(M + 127) / 128, 256, SMEM64>>>((const float*)p_y, W2, (float*)p_h, M);
    gather64_kernel<false><<<(M * 32 + 255) / 256, 256>>>(
        (const float*)p_h, b2, (float*)d_out, M);
}